// round 14
// baseline (speedup 1.0000x reference)
#include <cuda_runtime.h>
#include <cuda_bf16.h>
#include <cuda_fp16.h>
#include <math.h>
#include <stdint.h>

// Problem constants
#define NROWS  2048      // B*N
#define DMODEL 1024
#define NHEAD  16
#define DHEAD  64
#define DFF    4096
#define NVOCAB 32000
#define NLAYER 6

// weight scratch offsets (elements)
#define CNT_QKV  (6u*1024u*3072u)
#define CNT_WOUT (6u*1024u*1024u)
#define CNT_W1   (6u*1024u*4096u)
#define CNT_W2   (6u*1024u*4096u)
#define CNT_WLOG (1024u*32000u)
#define OFF_QKV  0u
#define OFF_WOUT (OFF_QKV + CNT_QKV)
#define OFF_W1   (OFF_WOUT + CNT_WOUT)
#define OFF_W2   (OFF_W1 + CNT_W1)
#define OFF_WLOG (OFF_W2 + CNT_W2)
#define CNT_WALL (OFF_WLOG + CNT_WLOG)

// ---------------- device scratch (no allocation allowed) ----------------
__device__ float g_h  [NROWS * DMODEL];
__device__ float g_qkv[NROWS * 3 * DMODEL];
__device__ __nv_bfloat16 g_xnh[NROWS * DMODEL], g_xnl[NROWS * DMODEL];
__device__ __nv_bfloat16 g_oh [NROWS * DMODEL], g_ol [NROWS * DMODEL];
__device__ __nv_bfloat16 g_ffh[NROWS * DFF],    g_ffl[NROWS * DFF];
__device__ __nv_bfloat16 g_wh [CNT_WALL];
__device__ __nv_bfloat16 g_wl [CNT_WALL];

// ---------------- helpers ----------------
__device__ __forceinline__ float geluf(float x) {
    return 0.5f * x * (1.0f + erff(x * 0.70710678118654752f));
}

__device__ __forceinline__ float bfr(float x) {
    return __bfloat162float(__float2bfloat16_rn(x));
}

__device__ __forceinline__ float block_sum256(float v, float* sred) {
#pragma unroll
    for (int o = 16; o > 0; o >>= 1) v += __shfl_xor_sync(0xffffffffu, v, o);
    int w = threadIdx.x >> 5;
    if ((threadIdx.x & 31) == 0) sred[w] = v;
    __syncthreads();
    float t = sred[threadIdx.x & 7];
#pragma unroll
    for (int o = 4; o > 0; o >>= 1) t += __shfl_xor_sync(0xffffffffu, t, o);
    __syncthreads();
    return t;
}

__device__ __forceinline__ uint32_t s2u(const void* p) {
    return (uint32_t)__cvta_generic_to_shared(p);
}

__device__ __forceinline__ uint32_t packbf(float a, float b) {
    __nv_bfloat162 t = __floats2bfloat162_rn(a, b);
    return *reinterpret_cast<uint32_t*>(&t);
}

__device__ __forceinline__ uint32_t packh(float a, float b) {
    __half2 t = __floats2half2_rn(a, b);
    return *reinterpret_cast<uint32_t*>(&t);
}

#define LDMX4(r, addr)                                                         \
    asm volatile("ldmatrix.sync.aligned.m8n8.x4.shared.b16 {%0,%1,%2,%3}, [%4];" \
        : "=r"((r)[0]), "=r"((r)[1]), "=r"((r)[2]), "=r"((r)[3]) : "r"(addr))

#define LDMX4T(r, addr)                                                        \
    asm volatile("ldmatrix.sync.aligned.m8n8.x4.trans.shared.b16 {%0,%1,%2,%3}, [%4];" \
        : "=r"((r)[0]), "=r"((r)[1]), "=r"((r)[2]), "=r"((r)[3]) : "r"(addr))

#define MMA16816(d, a, b0, b1)                                                 \
    asm volatile("mma.sync.aligned.m16n8k16.row.col.f32.bf16.bf16.f32 "        \
        "{%0,%1,%2,%3}, {%4,%5,%6,%7}, {%8,%9}, {%0,%1,%2,%3};"                \
        : "+f"((d)[0]), "+f"((d)[1]), "+f"((d)[2]), "+f"((d)[3])               \
        : "r"((a)[0]), "r"((a)[1]), "r"((a)[2]), "r"((a)[3]), "r"(b0), "r"(b1))

#define MMAF16(d, a, b0, b1)                                                   \
    asm volatile("mma.sync.aligned.m16n8k16.row.col.f32.f16.f16.f32 "          \
        "{%0,%1,%2,%3}, {%4,%5,%6,%7}, {%8,%9}, {%0,%1,%2,%3};"                \
        : "+f"((d)[0]), "+f"((d)[1]), "+f"((d)[2]), "+f"((d)[3])               \
        : "r"((a)[0]), "r"((a)[1]), "r"((a)[2]), "r"((a)[3]), "r"(b0), "r"(b1))

#define CP16(dst, src)                                                         \
    asm volatile("cp.async.cg.shared.global [%0], [%1], 16;" :: "r"(dst), "l"(src))
#define CPCOMMIT() asm volatile("cp.async.commit_group;")
#define CPWAIT(n)  asm volatile("cp.async.wait_group %0;" :: "n"(n))

// ---------------- weight split: fp32 -> bf16 hi + lo ----------------
__global__ __launch_bounds__(256) void wcvt_kernel(
    const float* __restrict__ src, __nv_bfloat16* __restrict__ dh,
    __nv_bfloat16* __restrict__ dl, int n4)
{
    int i = blockIdx.x * 256 + threadIdx.x;
    if (i >= n4) return;
    float4 v = ((const float4*)src)[i];
    float h0 = bfr(v.x), h1 = bfr(v.y), h2 = bfr(v.z), h3 = bfr(v.w);
    ((uint2*)dh)[i] = make_uint2(packbf(h0, h1), packbf(h2, h3));
    ((uint2*)dl)[i] = make_uint2(packbf(v.x - h0, v.y - h1),
                                 packbf(v.z - h2, v.w - h3));
}

// ---------------- weight convert: fp32 -> fp16 (single) ----------------
__global__ __launch_bounds__(256) void wcvt_h_kernel(
    const float* __restrict__ src, __half* __restrict__ dh, int n4)
{
    int i = blockIdx.x * 256 + threadIdx.x;
    if (i >= n4) return;
    float4 v = ((const float4*)src)[i];
    ((uint2*)dh)[i] = make_uint2(packh(v.x, v.y), packh(v.z, v.w));
}

// ---------------- embedding: h = token_emb[x] + pos_emb ----------------
__global__ __launch_bounds__(256) void embed_kernel(
    const int* __restrict__ x, const float* __restrict__ tok,
    const float* __restrict__ pos, float* __restrict__ h)
{
    int i = blockIdx.x * 256 + threadIdx.x;
    int row = i >> 8;
    int d4  = i & 255;
    int n = row & 1023;
    int t = x[row];
    float4 a = ((const float4*)(tok + (size_t)t * DMODEL))[d4];
    float4 p = ((const float4*)(pos + (size_t)n * DMODEL))[d4];
    a.x += p.x; a.y += p.y; a.z += p.z; a.w += p.w;
    ((float4*)(h + (size_t)row * DMODEL))[d4] = a;
}

// ---------------- layernorm -> bf16 hi/lo output ----------------
__global__ __launch_bounds__(256) void ln_kernel(
    const float* __restrict__ in,
    __nv_bfloat16* __restrict__ outh, __nv_bfloat16* __restrict__ outl,
    const float* __restrict__ gw, const float* __restrict__ bw)
{
    __shared__ float sred[8];
    const int row = blockIdx.x;
    const int tid = threadIdx.x;
    float4 v = ((const float4*)(in + (size_t)row * DMODEL))[tid];
    float s = v.x + v.y + v.z + v.w;
    float tot = block_sum256(s, sred);
    float mean = tot * (1.0f / (float)DMODEL);
    float d0 = v.x - mean, d1 = v.y - mean, d2 = v.z - mean, d3 = v.w - mean;
    float s2 = d0 * d0 + d1 * d1 + d2 * d2 + d3 * d3;
    float tot2 = block_sum256(s2, sred);
    float var = tot2 * (1.0f / (float)DMODEL);
    float rstd = rsqrtf(var + 1e-5f);
    float4 gg = ((const float4*)gw)[tid];
    float4 bb = ((const float4*)bw)[tid];
    float o0 = d0 * rstd * gg.x + bb.x;
    float o1 = d1 * rstd * gg.y + bb.y;
    float o2 = d2 * rstd * gg.z + bb.z;
    float o3 = d3 * rstd * gg.w + bb.w;
    float h0 = bfr(o0), h1 = bfr(o1), h2 = bfr(o2), h3 = bfr(o3);
    int idx = row * 256 + tid;
    ((uint2*)outh)[idx] = make_uint2(packbf(o0, o1), packbf(o2, o3));
    ((uint2*)outl)[idx] = make_uint2(packbf(o0 - h0, o1 - h1),
                                     packbf(o2 - h2, o3 - h3));
}

// ---------------- final layernorm -> fp16 hi/lo output ----------------
__global__ __launch_bounds__(256) void ln_h_kernel(
    const float* __restrict__ in,
    __half* __restrict__ outh, __half* __restrict__ outl,
    const float* __restrict__ gw, const float* __restrict__ bw)
{
    __shared__ float sred[8];
    const int row = blockIdx.x;
    const int tid = threadIdx.x;
    float4 v = ((const float4*)(in + (size_t)row * DMODEL))[tid];
    float s = v.x + v.y + v.z + v.w;
    float tot = block_sum256(s, sred);
    float mean = tot * (1.0f / (float)DMODEL);
    float d0 = v.x - mean, d1 = v.y - mean, d2 = v.z - mean, d3 = v.w - mean;
    float s2 = d0 * d0 + d1 * d1 + d2 * d2 + d3 * d3;
    float tot2 = block_sum256(s2, sred);
    float var = tot2 * (1.0f / (float)DMODEL);
    float rstd = rsqrtf(var + 1e-5f);
    float4 gg = ((const float4*)gw)[tid];
    float4 bb = ((const float4*)bw)[tid];
    float o0 = d0 * rstd * gg.x + bb.x;
    float o1 = d1 * rstd * gg.y + bb.y;
    float o2 = d2 * rstd * gg.z + bb.z;
    float o3 = d3 * rstd * gg.w + bb.w;
    float h0 = __half2float(__float2half_rn(o0));
    float h1 = __half2float(__float2half_rn(o1));
    float h2 = __half2float(__float2half_rn(o2));
    float h3 = __half2float(__float2half_rn(o3));
    int idx = row * 256 + tid;
    ((uint2*)outh)[idx] = make_uint2(packh(o0, o1), packh(o2, o3));
    ((uint2*)outl)[idx] = make_uint2(packh(o0 - h0, o1 - h1),
                                     packh(o2 - h2, o3 - h3));
}

// ---------------- flash attention v4: double-buffered K/V, 1 sync/tile ------
// qkv comes in with q,k already l2-normalized (fused into QKV GEMM epilogue).
__global__ __launch_bounds__(256) void flash_kernel(
    const float* __restrict__ qkv,
    __nv_bfloat16* __restrict__ oh, __nv_bfloat16* __restrict__ ol)
{
    __shared__ float Qs[64 * 68];
    __shared__ float Kt[2][64 * 32];   // [buf][d][j]
    __shared__ float Vs[2][32 * 64];   // [buf][j][d]
    __shared__ float Ps[64 * 36];

    const int bh = blockIdx.x;
    const int qb = 15 - blockIdx.y;   // longest blocks first
    const int b = bh >> 4, h = bh & 15;
    const int tid = threadIdx.x;
    const int r = tid >> 2;
    const int g = tid & 3;

    const float* qbase = qkv + (size_t)b * 1024 * (3 * DMODEL) + h * DHEAD;
    const float* kbase = qbase + DMODEL;
    const float* vbase = qbase + 2 * DMODEL;

    for (int t = tid; t < 64 * 16; t += 256) {
        int row = t >> 4;
        int d4  = (t & 15) << 2;
        float4 v = *(const float4*)(qbase + (size_t)(qb * 64 + row) * (3 * DMODEL) + d4);
        *(float4*)(&Qs[row * 68 + d4]) = v;
    }

    float lsum_t = 0.f;
    float acc[16];
#pragma unroll
    for (int i = 0; i < 16; i++) acc[i] = 0.f;

    const int iglob = qb * 64 + r;
    const int nkb = 2 * (qb + 1);
    const int c0 = g * 8;
    const int dd0 = g * 16;

    const int krow = tid & 31;
    const int kd4a = (tid >> 5) << 2;
    const int kd4b = kd4a + 32;
    const int vrowa = tid >> 4;
    const int vrowb = vrowa + 16;
    const int vd4  = (tid & 15) << 2;

    float4 kreg0 = *(const float4*)(kbase + (size_t)krow * 3072 + kd4a);
    float4 kreg1 = *(const float4*)(kbase + (size_t)krow * 3072 + kd4b);
    float4 vreg0 = *(const float4*)(vbase + (size_t)vrowa * 3072 + vd4);
    float4 vreg1 = *(const float4*)(vbase + (size_t)vrowb * 3072 + vd4);

    for (int kb = 0; kb < nkb; kb++) {
        float* KT = Kt[kb & 1];
        float* VS = Vs[kb & 1];
        KT[(kd4a + 0) * 32 + krow] = kreg0.x;
        KT[(kd4a + 1) * 32 + krow] = kreg0.y;
        KT[(kd4a + 2) * 32 + krow] = kreg0.z;
        KT[(kd4a + 3) * 32 + krow] = kreg0.w;
        KT[(kd4b + 0) * 32 + krow] = kreg1.x;
        KT[(kd4b + 1) * 32 + krow] = kreg1.y;
        KT[(kd4b + 2) * 32 + krow] = kreg1.z;
        KT[(kd4b + 3) * 32 + krow] = kreg1.w;
        *(float4*)(&VS[vrowa * 64 + vd4]) = vreg0;
        *(float4*)(&VS[vrowb * 64 + vd4]) = vreg1;
        __syncthreads();

        if (kb + 1 < nkb) {
            size_t ko = (size_t)((kb + 1) * 32);
            kreg0 = *(const float4*)(kbase + (ko + krow) * 3072 + kd4a);
            kreg1 = *(const float4*)(kbase + (ko + krow) * 3072 + kd4b);
            vreg0 = *(const float4*)(vbase + (ko + vrowa) * 3072 + vd4);
            vreg1 = *(const float4*)(vbase + (ko + vrowb) * 3072 + vd4);
        }

        float s[8];
#pragma unroll
        for (int j = 0; j < 8; j++) s[j] = 0.f;
#pragma unroll 4
        for (int d = 0; d < 64; d++) {
            float qd = Qs[r * 68 + d];
            float4 k0 = *(const float4*)(&KT[d * 32 + c0]);
            float4 k1 = *(const float4*)(&KT[d * 32 + c0 + 4]);
            s[0] = fmaf(qd, k0.x, s[0]); s[1] = fmaf(qd, k0.y, s[1]);
            s[2] = fmaf(qd, k0.z, s[2]); s[3] = fmaf(qd, k0.w, s[3]);
            s[4] = fmaf(qd, k1.x, s[4]); s[5] = fmaf(qd, k1.y, s[5]);
            s[6] = fmaf(qd, k1.z, s[6]); s[7] = fmaf(qd, k1.w, s[7]);
        }
        float ls = 0.f;
#pragma unroll
        for (int j = 0; j < 8; j++) {
            int jg = kb * 32 + c0 + j;
            float p = (jg <= iglob) ? __expf(fmaf(s[j], 8.0f, -8.0f)) : 0.f;
            s[j] = p;
            ls += p;
        }
        lsum_t += ls;
        *(float4*)(&Ps[r * 36 + c0])     = make_float4(s[0], s[1], s[2], s[3]);
        *(float4*)(&Ps[r * 36 + c0 + 4]) = make_float4(s[4], s[5], s[6], s[7]);
        __syncwarp();

        for (int j = 0; j < 32; j++) {
            float p = Ps[r * 36 + j];
            const float4* v4 = (const float4*)(&VS[j * 64 + dd0]);
            float4 v0 = v4[0], v1 = v4[1], v2 = v4[2], v3 = v4[3];
            acc[0]  = fmaf(p, v0.x, acc[0]);  acc[1]  = fmaf(p, v0.y, acc[1]);
            acc[2]  = fmaf(p, v0.z, acc[2]);  acc[3]  = fmaf(p, v0.w, acc[3]);
            acc[4]  = fmaf(p, v1.x, acc[4]);  acc[5]  = fmaf(p, v1.y, acc[5]);
            acc[6]  = fmaf(p, v1.z, acc[6]);  acc[7]  = fmaf(p, v1.w, acc[7]);
            acc[8]  = fmaf(p, v2.x, acc[8]);  acc[9]  = fmaf(p, v2.y, acc[9]);
            acc[10] = fmaf(p, v2.z, acc[10]); acc[11] = fmaf(p, v2.w, acc[11]);
            acc[12] = fmaf(p, v3.x, acc[12]); acc[13] = fmaf(p, v3.y, acc[13]);
            acc[14] = fmaf(p, v3.z, acc[14]); acc[15] = fmaf(p, v3.w, acc[15]);
        }
    }

    lsum_t += __shfl_xor_sync(0xffffffffu, lsum_t, 1, 32);
    lsum_t += __shfl_xor_sync(0xffffffffu, lsum_t, 2, 32);
    float inv = 1.f / lsum_t;

    size_t obase = (size_t)(b * 1024 + iglob) * DMODEL + h * DHEAD + dd0;
#pragma unroll
    for (int q = 0; q < 4; q++) {
        float v0 = acc[q * 4]     * inv;
        float v1 = acc[q * 4 + 1] * inv;
        float v2 = acc[q * 4 + 2] * inv;
        float v3 = acc[q * 4 + 3] * inv;
        float h0 = bfr(v0), h1 = bfr(v1), h2 = bfr(v2), h3 = bfr(v3);
        *(uint2*)(oh + obase + q * 4) = make_uint2(packbf(v0, v1), packbf(v2, v3));
        *(uint2*)(ol + obase + q * 4) = make_uint2(packbf(v0 - h0, v1 - h1),
                                                   packbf(v2 - h2, v3 - h3));
    }
}

// ---------------- 3xBF16 mma.sync GEMM ---------------------------------------
// 128 x BN x 32 tiles; BN=64 uses 3-stage pipeline, BN=128 2-stage.
// EPI: 1=+bias, 2=+bias+gelu->bf16 hi/lo, 3=+residual, 4=+bias+residual,
//      5=QKV: l2-normalize rows of q/k head tiles (bn<32), plain store for v.
template<int EPI, int BN>
__global__ __launch_bounds__(256, 2) void hgemm2_kernel(
    const __nv_bfloat16* __restrict__ Ah_g, const __nv_bfloat16* __restrict__ Al_g,
    const __nv_bfloat16* __restrict__ Bh_g, const __nv_bfloat16* __restrict__ Bl_g,
    float* __restrict__ C,
    __nv_bfloat16* __restrict__ Ch, __nv_bfloat16* __restrict__ Cl,
    int K, int N, const float* __restrict__ bias, const float* __restrict__ res)
{
    constexpr int      BP     = (BN == 128) ? 136 : 72;
    constexpr int      NT     = BN / 16;
    constexpr int      STAGES = (BN == 64) ? 3 : 2;
    constexpr uint32_t AL_OFF = 10240;
    constexpr uint32_t BH_OFF = 20480;
    constexpr uint32_t BBYT   = 32u * BP * 2u;
    constexpr uint32_t STG    = BH_OFF + 2u * BBYT;

    extern __shared__ char smem[];
    __shared__ float rnorm[128];
    const uint32_t sbase = s2u(smem);
    const int tid  = threadIdx.x;
    const int bn   = blockIdx.x, bm = blockIdx.y;
    const int lane = tid & 31, warp = tid >> 5;
    const int wm   = warp & 3;
    const int wn   = warp >> 2;

    float acc[2][NT][4] = {};

    const int ar0 = tid >> 2;
    const int as0 = (tid & 3) * 8;
    const __nv_bfloat16* gAh0 = Ah_g + (size_t)(bm * 128 + ar0) * K + as0;
    const __nv_bfloat16* gAh1 = gAh0 + (size_t)64 * K;
    const __nv_bfloat16* gAl0 = Al_g + (size_t)(bm * 128 + ar0) * K + as0;
    const __nv_bfloat16* gAl1 = gAl0 + (size_t)64 * K;
    const uint32_t dA0 = sbase + (uint32_t)(ar0 * 40 + as0) * 2;
    const uint32_t dA1 = sbase + (uint32_t)((ar0 + 64) * 40 + as0) * 2;

    const int bk0 = (BN == 128) ? (tid >> 4) : (tid >> 3);
    const int bs0 = (BN == 128) ? (tid & 15) * 8 : (tid & 7) * 8;
    const __nv_bfloat16* gBh0 = Bh_g + (size_t)bk0 * N + (size_t)bn * BN + bs0;
    const __nv_bfloat16* gBh1 = gBh0 + (size_t)16 * N;
    const __nv_bfloat16* gBl0 = Bl_g + (size_t)bk0 * N + (size_t)bn * BN + bs0;
    const __nv_bfloat16* gBl1 = gBl0 + (size_t)16 * N;
    const uint32_t dB0 = sbase + BH_OFF + (uint32_t)(bk0 * BP + bs0) * 2;
    const uint32_t dB1 = sbase + BH_OFF + (uint32_t)((bk0 + 16) * BP + bs0) * 2;

#define ISSUE_STAGE(stage, kt) do {                                            \
        uint32_t sb_ = (uint32_t)(stage) * STG;                                \
        size_t ko_ = (size_t)(kt);                                             \
        size_t kb_ = (size_t)(kt) * (size_t)N;                                 \
        CP16(dA0 + sb_,           gAh0 + ko_);                                 \
        CP16(dA1 + sb_,           gAh1 + ko_);                                 \
        CP16(dA0 + sb_ + AL_OFF,  gAl0 + ko_);                                 \
        CP16(dA1 + sb_ + AL_OFF,  gAl1 + ko_);                                 \
        CP16(dB0 + sb_,           gBh0 + kb_);                                 \
        CP16(dB0 + sb_ + BBYT,    gBl0 + kb_);                                 \
        if (BN == 128) {                                                       \
            CP16(dB1 + sb_,        gBh1 + kb_);                                \
            CP16(dB1 + sb_ + BBYT, gBl1 + kb_);                                \
        }                                                                      \
        CPCOMMIT();                                                            \
    } while (0)

    uint32_t aH[2], aL[2], bHa[NT / 2], bLa[NT / 2];
    {
        int r = wm * 32 + (lane & 7) + ((lane >> 3) & 1) * 8;
        int c = (lane >> 4) * 8;
        aH[0] = sbase + (uint32_t)(r * 40 + c) * 2;
        aH[1] = sbase + (uint32_t)((r + 16) * 40 + c) * 2;
        aL[0] = aH[0] + AL_OFF;
        aL[1] = aH[1] + AL_OFF;
        int br = (lane & 7) + ((lane >> 3) & 1) * 8;
        int bc = wn * (BN / 2) + (lane >> 4) * 8;
#pragma unroll
        for (int p = 0; p < NT / 2; p++) {
            bHa[p] = sbase + BH_OFF + (uint32_t)(br * BP + bc + p * 16) * 2;
            bLa[p] = bHa[p] + BBYT;
        }
    }

    const int nc = K >> 5;
    ISSUE_STAGE(0, 0);
    if (STAGES == 3) ISSUE_STAGE(1, 32);

    for (int cchunk = 0; cchunk < nc; cchunk++) {
        const uint32_t sb = (uint32_t)(cchunk % STAGES) * STG;
        if (STAGES == 3 && cchunk < nc - 1) { CPWAIT(1); }
        else                                { CPWAIT(0); }
        __syncthreads();
        int nxt = cchunk + STAGES - 1;
        if (nxt < nc) ISSUE_STAGE(nxt % STAGES, nxt * 32);

#pragma unroll
        for (int ks = 0; ks < 2; ks++) {
            const uint32_t ao = sb + ks * 32;
            const uint32_t bo = sb + ks * (16u * BP * 2u);
            uint32_t a_h[2][4], a_l[2][4], bfrg[NT / 2][4];
            LDMX4(a_h[0], aH[0] + ao);
            LDMX4(a_h[1], aH[1] + ao);
            LDMX4(a_l[0], aL[0] + ao);
            LDMX4(a_l[1], aL[1] + ao);
#pragma unroll
            for (int p = 0; p < NT / 2; p++) LDMX4T(bfrg[p], bHa[p] + bo);
#pragma unroll
            for (int mt = 0; mt < 2; mt++)
#pragma unroll
                for (int nt = 0; nt < NT; nt++) {
                    uint32_t b0 = bfrg[nt >> 1][(nt & 1) * 2];
                    uint32_t b1 = bfrg[nt >> 1][(nt & 1) * 2 + 1];
                    MMA16816(acc[mt][nt], a_h[mt], b0, b1);
                    MMA16816(acc[mt][nt], a_l[mt], b0, b1);
                }
#pragma unroll
            for (int p = 0; p < NT / 2; p++) LDMX4T(bfrg[p], bLa[p] + bo);
#pragma unroll
            for (int mt = 0; mt < 2; mt++)
#pragma unroll
                for (int nt = 0; nt < NT; nt++) {
                    uint32_t b0 = bfrg[nt >> 1][(nt & 1) * 2];
                    uint32_t b1 = bfrg[nt >> 1][(nt & 1) * 2 + 1];
                    MMA16816(acc[mt][nt], a_h[mt], b0, b1);
                }
        }
    }
#undef ISSUE_STAGE

    const int g  = lane >> 2;
    const int tg = lane & 3;

    if (EPI == 5) {
        // QKV epilogue: l2-normalize q/k head rows (one head per BN=64 tile).
        const bool dn = (bn < 32);
        if (dn) {
            if (tid < 128) rnorm[tid] = 0.f;
            __syncthreads();
#pragma unroll
            for (int mt = 0; mt < 2; mt++) {
                float s0 = 0.f, s1 = 0.f;
#pragma unroll
                for (int nt = 0; nt < NT; nt++) {
                    s0 += acc[mt][nt][0] * acc[mt][nt][0]
                        + acc[mt][nt][1] * acc[mt][nt][1];
                    s1 += acc[mt][nt][2] * acc[mt][nt][2]
                        + acc[mt][nt][3] * acc[mt][nt][3];
                }
                int rl = wm * 32 + mt * 16 + g;
                atomicAdd(&rnorm[rl], s0);
                atomicAdd(&rnorm[rl + 8], s1);
            }
            __syncthreads();
        }
#pragma unroll
        for (int mt = 0; mt < 2; mt++) {
            int rl = wm * 32 + mt * 16 + g;
            int row = bm * 128 + rl;
            float i0 = dn ? rsqrtf(rnorm[rl])     : 1.f;
            float i1 = dn ? rsqrtf(rnorm[rl + 8]) : 1.f;
#pragma unroll
            for (int nt = 0; nt < NT; nt++) {
                int col = bn * BN + wn * (BN / 2) + nt * 8 + tg * 2;
                size_t off0 = (size_t)row * N + col;
                size_t off1 = (size_t)(row + 8) * N + col;
                *(float2*)(C + off0) = make_float2(acc[mt][nt][0] * i0,
                                                   acc[mt][nt][1] * i0);
                *(float2*)(C + off1) = make_float2(acc[mt][nt][2] * i1,
                                                   acc[mt][nt][3] * i1);
            }
        }
    } else {
#pragma unroll
        for (int mt = 0; mt < 2; mt++) {
            int row = bm * 128 + wm * 32 + mt * 16 + g;
#pragma unroll
            for (int nt = 0; nt < NT; nt++) {
                int col = bn * BN + wn * (BN / 2) + nt * 8 + tg * 2;
                float d0 = acc[mt][nt][0], d1 = acc[mt][nt][1];
                float d2 = acc[mt][nt][2], d3 = acc[mt][nt][3];
                if (EPI == 1 || EPI == 2 || EPI == 4) {
                    float2 bb = *(const float2*)(bias + col);
                    d0 += bb.x; d1 += bb.y; d2 += bb.x; d3 += bb.y;
                }
                size_t off0 = (size_t)row * N + col;
                size_t off1 = (size_t)(row + 8) * N + col;
                if (EPI == 2) {
                    d0 = geluf(d0); d1 = geluf(d1); d2 = geluf(d2); d3 = geluf(d3);
                    float h0 = bfr(d0), h1 = bfr(d1), h2 = bfr(d2), h3 = bfr(d3);
                    *(uint32_t*)(Ch + off0) = packbf(d0, d1);
                    *(uint32_t*)(Cl + off0) = packbf(d0 - h0, d1 - h1);
                    *(uint32_t*)(Ch + off1) = packbf(d2, d3);
                    *(uint32_t*)(Cl + off1) = packbf(d2 - h2, d3 - h3);
                } else {
                    if (EPI == 3 || EPI == 4) {
                        float2 r0 = *(const float2*)(res + off0);
                        float2 r1 = *(const float2*)(res + off1);
                        d0 += r0.x; d1 += r0.y; d2 += r1.x; d3 += r1.y;
                    }
                    *(float2*)(C + off0) = make_float2(d0, d1);
                    *(float2*)(C + off1) = make_float2(d2, d3);
                }
            }
        }
    }
}

// ---------------- 2xFP16 mma.sync GEMM for logits ---------------------------
// Grid: (bm, bn) with bm fastest so consecutive CTAs share the B tile in L2.
__global__ __launch_bounds__(256, 2) void hgemm_h2_kernel(
    const __half* __restrict__ Ah_g, const __half* __restrict__ Al_g,
    const __half* __restrict__ Bh_g, float* __restrict__ C,
    int K, int N, const float* __restrict__ bias)
{
    constexpr int      BP     = 136;
    constexpr uint32_t AL_OFF = 10240;
    constexpr uint32_t BH_OFF = 20480;
    constexpr uint32_t BBYT   = 32u * BP * 2u;     // 8704
    constexpr uint32_t STG    = BH_OFF + BBYT;     // 29184

    extern __shared__ char smem[];
    const uint32_t sbase = s2u(smem);
    const int tid  = threadIdx.x;
    const int bm   = blockIdx.x, bn = blockIdx.y;   // bm fastest: B-tile L2 reuse
    const int lane = tid & 31, warp = tid >> 5;
    const int wm   = warp & 3;
    const int wn   = warp >> 2;

    float acc[2][8][4] = {};

    const int ar0 = tid >> 2;
    const int as0 = (tid & 3) * 8;
    const __half* gAh0 = Ah_g + (size_t)(bm * 128 + ar0) * K + as0;
    const __half* gAh1 = gAh0 + (size_t)64 * K;
    const __half* gAl0 = Al_g + (size_t)(bm * 128 + ar0) * K + as0;
    const __half* gAl1 = gAl0 + (size_t)64 * K;
    const uint32_t dA0 = sbase + (uint32_t)(ar0 * 40 + as0) * 2;
    const uint32_t dA1 = sbase + (uint32_t)((ar0 + 64) * 40 + as0) * 2;

    const int bk0 = tid >> 4;
    const int bs0 = (tid & 15) * 8;
    const __half* gBh0 = Bh_g + (size_t)bk0 * N + (size_t)bn * 128 + bs0;
    const __half* gBh1 = gBh0 + (size_t)16 * N;
    const uint32_t dB0 = sbase + BH_OFF + (uint32_t)(bk0 * BP + bs0) * 2;
    const uint32_t dB1 = sbase + BH_OFF + (uint32_t)((bk0 + 16) * BP + bs0) * 2;

#define ISSUE_H(stage, kt) do {                                                \
        uint32_t sb_ = (uint32_t)(stage) * STG;                                \
        size_t ko_ = (size_t)(kt);                                             \
        size_t kb_ = (size_t)(kt) * (size_t)N;                                 \
        CP16(dA0 + sb_,          gAh0 + ko_);                                  \
        CP16(dA1 + sb_,          gAh1 + ko_);                                  \
        CP16(dA0 + sb_ + AL_OFF, gAl0 + ko_);                                  \
        CP16(dA1 + sb_ + AL_OFF, gAl1 + ko_);                                  \
        CP16(dB0 + sb_,          gBh0 + kb_);                                  \
        CP16(dB1 + sb_,          gBh1 + kb_);                                  \
        CPCOMMIT();                                                            \
    } while (0)

    uint32_t aH[2], aL[2], bHa[4];
    {
        int r = wm * 32 + (lane & 7) + ((lane >> 3) & 1) * 8;
        int c = (lane >> 4) * 8;
        aH[0] = sbase + (uint32_t)(r * 40 + c) * 2;
        aH[1] = sbase + (uint32_t)((r + 16) * 40 + c) * 2;
        aL[0] = aH[0] + AL_OFF;
        aL[1] = aH[1] + AL_OFF;
        int br = (lane & 7) + ((lane >> 3) & 1) * 8;
        int bc = wn * 64 + (lane >> 4) * 8;
#pragma unroll
        for (int p = 0; p < 4; p++)
            bHa[p] = sbase + BH_OFF + (uint32_t)(br * BP + bc + p * 16) * 2;
    }

    const int nc = K >> 5;
    ISSUE_H(0, 0);

    for (int cchunk = 0; cchunk < nc; cchunk++) {
        const uint32_t sb = (uint32_t)(cchunk & 1) * STG;
        CPWAIT(0);
        __syncthreads();
        if (cchunk + 1 < nc) ISSUE_H((cchunk + 1) & 1, (cchunk + 1) * 32);

#pragma unroll
        for (int ks = 0; ks < 2; ks++) {
            const uint32_t ao = sb + ks * 32;
            const uint32_t bo = sb + ks * (16u * BP * 2u);
            uint32_t a_h[2][4], a_l[2][4], bfrg[4][4];
            LDMX4(a_h[0], aH[0] + ao);
            LDMX4(a_h[1], aH[1] + ao);
            LDMX4(a_l[0], aL[0] + ao);
            LDMX4(a_l[1], aL[1] + ao);
#pragma unroll
            for (int p = 0; p < 4; p++) LDMX4T(bfrg[p], bHa[p] + bo);
#pragma unroll
            for (int mt = 0; mt < 2; mt++)
#pragma unroll
                for (int nt = 0; nt < 8; nt++) {
                    uint32_t b0 = bfrg[nt >> 1][(nt & 1) * 2];
                    uint32_t b1 = bfrg[nt >> 1][(nt & 1) * 2 + 1];
                    MMAF16(acc[mt][nt], a_h[mt], b0, b1);
                    MMAF16(acc[mt][nt], a_l[mt], b0, b1);
                }
        }
    }
#undef ISSUE_H

    const int g  = lane >> 2;
    const int tg = lane & 3;
#pragma unroll
    for (int mt = 0; mt < 2; mt++) {
        int row = bm * 128 + wm * 32 + mt * 16 + g;
#pragma unroll
        for (int nt = 0; nt < 8; nt++) {
            int col = bn * 128 + wn * 64 + nt * 8 + tg * 2;
            float2 bb = *(const float2*)(bias + col);
            float d0 = acc[mt][nt][0] + bb.x, d1 = acc[mt][nt][1] + bb.y;
            float d2 = acc[mt][nt][2] + bb.x, d3 = acc[mt][nt][3] + bb.y;
            size_t off0 = (size_t)row * N + col;
            size_t off1 = (size_t)(row + 8) * N + col;
            *(float2*)(C + off0) = make_float2(d0, d1);
            *(float2*)(C + off1) = make_float2(d2, d3);
        }
    }
}

#define STG128 (20480u + 2u * (32u * 136u * 2u))   // 37888
#define STG64  (20480u + 2u * (32u * 72u  * 2u))   // 29696
#define GSMEM128 (2 * STG128)                      // 75776
#define GSMEM64  (3 * STG64)                       // 89088 (3-stage)
#define GSMEMH   (2 * 29184u)                      // 58368

// ---------------- launch ----------------
extern "C" void kernel_launch(void* const* d_in, const int* in_sizes, int n_in,
                              void* d_out, int out_size)
{
    const int*   x       = (const int*)  d_in[0];
    const float* tok     = (const float*)d_in[1];
    const float* pos     = (const float*)d_in[2];
    const float* ln1_g   = (const float*)d_in[3];
    const float* ln1_b   = (const float*)d_in[4];
    const float* w_qkv   = (const float*)d_in[5];
    const float* w_out   = (const float*)d_in[6];
    const float* ln2_g   = (const float*)d_in[7];
    const float* ln2_b   = (const float*)d_in[8];
    const float* w1      = (const float*)d_in[9];
    const float* b1      = (const float*)d_in[10];
    const float* w2      = (const float*)d_in[11];
    const float* b2      = (const float*)d_in[12];
    const float* lnf_g   = (const float*)d_in[13];
    const float* lnf_b   = (const float*)d_in[14];
    const float* w_logit = (const float*)d_in[15];
    const float* b_logit = (const float*)d_in[16];
    float* out = (float*)d_out;

    void *ph, *pqkv, *pxnh, *pxnl, *poh, *pol, *pffh, *pffl, *pwh, *pwl;
    cudaGetSymbolAddress(&ph,   g_h);
    cudaGetSymbolAddress(&pqkv, g_qkv);
    cudaGetSymbolAddress(&pxnh, g_xnh);
    cudaGetSymbolAddress(&pxnl, g_xnl);
    cudaGetSymbolAddress(&poh,  g_oh);
    cudaGetSymbolAddress(&pol,  g_ol);
    cudaGetSymbolAddress(&pffh, g_ffh);
    cudaGetSymbolAddress(&pffl, g_ffl);
    cudaGetSymbolAddress(&pwh,  g_wh);
    cudaGetSymbolAddress(&pwl,  g_wl);
    float* h   = (float*)ph;
    float* qkv = (float*)pqkv;
    __nv_bfloat16* xnh = (__nv_bfloat16*)pxnh;
    __nv_bfloat16* xnl = (__nv_bfloat16*)pxnl;
    __nv_bfloat16* oh  = (__nv_bfloat16*)poh;
    __nv_bfloat16* ol  = (__nv_bfloat16*)pol;
    __nv_bfloat16* ffh = (__nv_bfloat16*)pffh;
    __nv_bfloat16* ffl = (__nv_bfloat16*)pffl;
    __nv_bfloat16* wh  = (__nv_bfloat16*)pwh;
    __nv_bfloat16* wl  = (__nv_bfloat16*)pwl;
    __half* xh2 = (__half*)pffh;
    __half* xl2 = (__half*)pffl;
    __half* wlh = (__half*)(wh + OFF_WLOG);

    cudaFuncSetAttribute(hgemm2_kernel<5,64>,  cudaFuncAttributeMaxDynamicSharedMemorySize, GSMEM64);
    cudaFuncSetAttribute(hgemm2_kernel<3,64>,  cudaFuncAttributeMaxDynamicSharedMemorySize, GSMEM64);
    cudaFuncSetAttribute(hgemm2_kernel<4,64>,  cudaFuncAttributeMaxDynamicSharedMemorySize, GSMEM64);
    cudaFuncSetAttribute(hgemm2_kernel<2,128>, cudaFuncAttributeMaxDynamicSharedMemorySize, GSMEM128);
    cudaFuncSetAttribute(hgemm_h2_kernel,      cudaFuncAttributeMaxDynamicSharedMemorySize, GSMEMH);

    // ---- weight splitting (once per launch) ----
    wcvt_kernel<<<(CNT_QKV  / 4 + 255) / 256, 256>>>(w_qkv,   wh + OFF_QKV,  wl + OFF_QKV,  CNT_QKV  / 4);
    wcvt_kernel<<<(CNT_WOUT / 4 + 255) / 256, 256>>>(w_out,   wh + OFF_WOUT, wl + OFF_WOUT, CNT_WOUT / 4);
    wcvt_kernel<<<(CNT_W1   / 4 + 255) / 256, 256>>>(w1,      wh + OFF_W1,   wl + OFF_W1,   CNT_W1   / 4);
    wcvt_kernel<<<(CNT_W2   / 4 + 255) / 256, 256>>>(w2,      wh + OFF_W2,   wl + OFF_W2,   CNT_W2   / 4);
    wcvt_h_kernel<<<(CNT_WLOG / 4 + 255) / 256, 256>>>(w_logit, wlh, CNT_WLOG / 4);

    embed_kernel<<<2048, 256>>>(x, tok, pos, h);

    for (int l = 0; l < NLAYER; l++) {
        ln_kernel<<<NROWS, 256>>>(h, xnh, xnl, ln1_g + l * DMODEL, ln1_b + l * DMODEL);
        // QKV with fused q/k l2norm in epilogue (EPI=5)
        hgemm2_kernel<5,64><<<dim3(3072 / 64, NROWS / 128), 256, GSMEM64>>>(
            xnh, xnl, wh + OFF_QKV + (size_t)l * 1024 * 3072, wl + OFF_QKV + (size_t)l * 1024 * 3072,
            qkv, nullptr, nullptr, DMODEL, 3072, nullptr, nullptr);
        flash_kernel<<<dim3(32, 16), 256>>>(qkv, oh, ol);
        hgemm2_kernel<3,64><<<dim3(DMODEL / 64, NROWS / 128), 256, GSMEM64>>>(
            oh, ol, wh + OFF_WOUT + (size_t)l * 1024 * 1024, wl + OFF_WOUT + (size_t)l * 1024 * 1024,
            h, nullptr, nullptr, DMODEL, DMODEL, nullptr, h);
        ln_kernel<<<NROWS, 256>>>(h, xnh, xnl, ln2_g + l * DMODEL, ln2_b + l * DMODEL);
        hgemm2_kernel<2,128><<<dim3(DFF / 128, NROWS / 128), 256, GSMEM128>>>(
            xnh, xnl, wh + OFF_W1 + (size_t)l * 1024 * 4096, wl + OFF_W1 + (size_t)l * 1024 * 4096,
            nullptr, ffh, ffl, DMODEL, DFF, b1 + l * DFF, nullptr);
        hgemm2_kernel<4,64><<<dim3(DMODEL / 64, NROWS / 128), 256, GSMEM64>>>(
            ffh, ffl, wh + OFF_W2 + (size_t)l * 1024 * 4096, wl + OFF_W2 + (size_t)l * 1024 * 4096,
            h, nullptr, nullptr, DFF, DMODEL, b2 + l * DMODEL, h);
    }

    // final LN -> fp16 hi/lo (ff buffers are dead after the last layer)
    ln_h_kernel<<<NROWS, 256>>>(h, xh2, xl2, lnf_g, lnf_b);
    // logits: bm fastest for B-tile L2 reuse
    hgemm_h2_kernel<<<dim3(NROWS / 128, NVOCAB / 128), 256, GSMEMH>>>(
        xh2, xl2, wlh, out, DMODEL, NVOCAB, b_logit);
}

// round 15
// speedup vs baseline: 1.0083x; 1.0083x over previous
#include <cuda_runtime.h>
#include <cuda_bf16.h>
#include <cuda_fp16.h>
#include <math.h>
#include <stdint.h>

// Problem constants
#define NROWS  2048      // B*N
#define DMODEL 1024
#define NHEAD  16
#define DHEAD  64
#define DFF    4096
#define NVOCAB 32000
#define NLAYER 6

// weight scratch offsets (elements)
#define CNT_QKV  (6u*1024u*3072u)
#define CNT_WOUT (6u*1024u*1024u)
#define CNT_W1   (6u*1024u*4096u)
#define CNT_W2   (6u*1024u*4096u)
#define CNT_WLOG (1024u*32000u)
#define OFF_QKV  0u
#define OFF_WOUT (OFF_QKV + CNT_QKV)
#define OFF_W1   (OFF_WOUT + CNT_WOUT)
#define OFF_W2   (OFF_W1 + CNT_W1)
#define OFF_WLOG (OFF_W2 + CNT_W2)
#define CNT_WALL (OFF_WLOG + CNT_WLOG)

// ---------------- device scratch (no allocation allowed) ----------------
__device__ float g_h  [NROWS * DMODEL];
__device__ float g_qkv[NROWS * 3 * DMODEL];
__device__ __nv_bfloat16 g_xnh[NROWS * DMODEL], g_xnl[NROWS * DMODEL];
__device__ __nv_bfloat16 g_oh [NROWS * DMODEL], g_ol [NROWS * DMODEL];
__device__ __nv_bfloat16 g_ffh[NROWS * DFF],    g_ffl[NROWS * DFF];
__device__ __nv_bfloat16 g_wh [CNT_WALL];
__device__ __nv_bfloat16 g_wl [CNT_WALL];

// ---------------- helpers ----------------
__device__ __forceinline__ float geluf(float x) {
    return 0.5f * x * (1.0f + erff(x * 0.70710678118654752f));
}

__device__ __forceinline__ float bfr(float x) {
    return __bfloat162float(__float2bfloat16_rn(x));
}

__device__ __forceinline__ float block_sum256(float v, float* sred) {
#pragma unroll
    for (int o = 16; o > 0; o >>= 1) v += __shfl_xor_sync(0xffffffffu, v, o);
    int w = threadIdx.x >> 5;
    if ((threadIdx.x & 31) == 0) sred[w] = v;
    __syncthreads();
    float t = sred[threadIdx.x & 7];
#pragma unroll
    for (int o = 4; o > 0; o >>= 1) t += __shfl_xor_sync(0xffffffffu, t, o);
    __syncthreads();
    return t;
}

__device__ __forceinline__ uint32_t s2u(const void* p) {
    return (uint32_t)__cvta_generic_to_shared(p);
}

__device__ __forceinline__ uint32_t packbf(float a, float b) {
    __nv_bfloat162 t = __floats2bfloat162_rn(a, b);
    return *reinterpret_cast<uint32_t*>(&t);
}

__device__ __forceinline__ uint32_t packh(float a, float b) {
    __half2 t = __floats2half2_rn(a, b);
    return *reinterpret_cast<uint32_t*>(&t);
}

#define LDMX4(r, addr)                                                         \
    asm volatile("ldmatrix.sync.aligned.m8n8.x4.shared.b16 {%0,%1,%2,%3}, [%4];" \
        : "=r"((r)[0]), "=r"((r)[1]), "=r"((r)[2]), "=r"((r)[3]) : "r"(addr))

#define LDMX4T(r, addr)                                                        \
    asm volatile("ldmatrix.sync.aligned.m8n8.x4.trans.shared.b16 {%0,%1,%2,%3}, [%4];" \
        : "=r"((r)[0]), "=r"((r)[1]), "=r"((r)[2]), "=r"((r)[3]) : "r"(addr))

#define MMA16816(d, a, b0, b1)                                                 \
    asm volatile("mma.sync.aligned.m16n8k16.row.col.f32.bf16.bf16.f32 "        \
        "{%0,%1,%2,%3}, {%4,%5,%6,%7}, {%8,%9}, {%0,%1,%2,%3};"                \
        : "+f"((d)[0]), "+f"((d)[1]), "+f"((d)[2]), "+f"((d)[3])               \
        : "r"((a)[0]), "r"((a)[1]), "r"((a)[2]), "r"((a)[3]), "r"(b0), "r"(b1))

#define MMAF16(d, a, b0, b1)                                                   \
    asm volatile("mma.sync.aligned.m16n8k16.row.col.f32.f16.f16.f32 "          \
        "{%0,%1,%2,%3}, {%4,%5,%6,%7}, {%8,%9}, {%0,%1,%2,%3};"                \
        : "+f"((d)[0]), "+f"((d)[1]), "+f"((d)[2]), "+f"((d)[3])               \
        : "r"((a)[0]), "r"((a)[1]), "r"((a)[2]), "r"((a)[3]), "r"(b0), "r"(b1))

#define CP16(dst, src)                                                         \
    asm volatile("cp.async.cg.shared.global [%0], [%1], 16;" :: "r"(dst), "l"(src))
#define CPCOMMIT() asm volatile("cp.async.commit_group;")
#define CPWAIT(n)  asm volatile("cp.async.wait_group %0;" :: "n"(n))

// ---------------- weight split: fp32 -> bf16 hi + lo ----------------
__global__ __launch_bounds__(256) void wcvt_kernel(
    const float* __restrict__ src, __nv_bfloat16* __restrict__ dh,
    __nv_bfloat16* __restrict__ dl, int n4)
{
    int i = blockIdx.x * 256 + threadIdx.x;
    if (i >= n4) return;
    float4 v = ((const float4*)src)[i];
    float h0 = bfr(v.x), h1 = bfr(v.y), h2 = bfr(v.z), h3 = bfr(v.w);
    ((uint2*)dh)[i] = make_uint2(packbf(h0, h1), packbf(h2, h3));
    ((uint2*)dl)[i] = make_uint2(packbf(v.x - h0, v.y - h1),
                                 packbf(v.z - h2, v.w - h3));
}

// ---------------- weight convert: fp32 -> fp16 (single) ----------------
__global__ __launch_bounds__(256) void wcvt_h_kernel(
    const float* __restrict__ src, __half* __restrict__ dh, int n4)
{
    int i = blockIdx.x * 256 + threadIdx.x;
    if (i >= n4) return;
    float4 v = ((const float4*)src)[i];
    ((uint2*)dh)[i] = make_uint2(packh(v.x, v.y), packh(v.z, v.w));
}

// ---------------- embedding: h = token_emb[x] + pos_emb ----------------
__global__ __launch_bounds__(256) void embed_kernel(
    const int* __restrict__ x, const float* __restrict__ tok,
    const float* __restrict__ pos, float* __restrict__ h)
{
    int i = blockIdx.x * 256 + threadIdx.x;
    int row = i >> 8;
    int d4  = i & 255;
    int n = row & 1023;
    int t = x[row];
    float4 a = ((const float4*)(tok + (size_t)t * DMODEL))[d4];
    float4 p = ((const float4*)(pos + (size_t)n * DMODEL))[d4];
    a.x += p.x; a.y += p.y; a.z += p.z; a.w += p.w;
    ((float4*)(h + (size_t)row * DMODEL))[d4] = a;
}

// ---------------- layernorm -> bf16 hi/lo output ----------------
__global__ __launch_bounds__(256) void ln_kernel(
    const float* __restrict__ in,
    __nv_bfloat16* __restrict__ outh, __nv_bfloat16* __restrict__ outl,
    const float* __restrict__ gw, const float* __restrict__ bw)
{
    __shared__ float sred[8];
    const int row = blockIdx.x;
    const int tid = threadIdx.x;
    float4 v = ((const float4*)(in + (size_t)row * DMODEL))[tid];
    float s = v.x + v.y + v.z + v.w;
    float tot = block_sum256(s, sred);
    float mean = tot * (1.0f / (float)DMODEL);
    float d0 = v.x - mean, d1 = v.y - mean, d2 = v.z - mean, d3 = v.w - mean;
    float s2 = d0 * d0 + d1 * d1 + d2 * d2 + d3 * d3;
    float tot2 = block_sum256(s2, sred);
    float var = tot2 * (1.0f / (float)DMODEL);
    float rstd = rsqrtf(var + 1e-5f);
    float4 gg = ((const float4*)gw)[tid];
    float4 bb = ((const float4*)bw)[tid];
    float o0 = d0 * rstd * gg.x + bb.x;
    float o1 = d1 * rstd * gg.y + bb.y;
    float o2 = d2 * rstd * gg.z + bb.z;
    float o3 = d3 * rstd * gg.w + bb.w;
    float h0 = bfr(o0), h1 = bfr(o1), h2 = bfr(o2), h3 = bfr(o3);
    int idx = row * 256 + tid;
    ((uint2*)outh)[idx] = make_uint2(packbf(o0, o1), packbf(o2, o3));
    ((uint2*)outl)[idx] = make_uint2(packbf(o0 - h0, o1 - h1),
                                     packbf(o2 - h2, o3 - h3));
}

// ---------------- final layernorm -> fp16 hi/lo output ----------------
__global__ __launch_bounds__(256) void ln_h_kernel(
    const float* __restrict__ in,
    __half* __restrict__ outh, __half* __restrict__ outl,
    const float* __restrict__ gw, const float* __restrict__ bw)
{
    __shared__ float sred[8];
    const int row = blockIdx.x;
    const int tid = threadIdx.x;
    float4 v = ((const float4*)(in + (size_t)row * DMODEL))[tid];
    float s = v.x + v.y + v.z + v.w;
    float tot = block_sum256(s, sred);
    float mean = tot * (1.0f / (float)DMODEL);
    float d0 = v.x - mean, d1 = v.y - mean, d2 = v.z - mean, d3 = v.w - mean;
    float s2 = d0 * d0 + d1 * d1 + d2 * d2 + d3 * d3;
    float tot2 = block_sum256(s2, sred);
    float var = tot2 * (1.0f / (float)DMODEL);
    float rstd = rsqrtf(var + 1e-5f);
    float4 gg = ((const float4*)gw)[tid];
    float4 bb = ((const float4*)bw)[tid];
    float o0 = d0 * rstd * gg.x + bb.x;
    float o1 = d1 * rstd * gg.y + bb.y;
    float o2 = d2 * rstd * gg.z + bb.z;
    float o3 = d3 * rstd * gg.w + bb.w;
    float h0 = __half2float(__float2half_rn(o0));
    float h1 = __half2float(__float2half_rn(o1));
    float h2 = __half2float(__float2half_rn(o2));
    float h3 = __half2float(__float2half_rn(o3));
    int idx = row * 256 + tid;
    ((uint2*)outh)[idx] = make_uint2(packh(o0, o1), packh(o2, o3));
    ((uint2*)outl)[idx] = make_uint2(packh(o0 - h0, o1 - h1),
                                     packh(o2 - h2, o3 - h3));
}

// ---------------- flash attention v4: double-buffered K/V, 1 sync/tile ------
// qkv comes in with q,k already l2-normalized (fused into QKV GEMM epilogue).
__global__ __launch_bounds__(256) void flash_kernel(
    const float* __restrict__ qkv,
    __nv_bfloat16* __restrict__ oh, __nv_bfloat16* __restrict__ ol)
{
    __shared__ float Qs[64 * 68];
    __shared__ float Kt[2][64 * 32];   // [buf][d][j]
    __shared__ float Vs[2][32 * 64];   // [buf][j][d]
    __shared__ float Ps[64 * 36];

    const int bh = blockIdx.x;
    const int qb = 15 - blockIdx.y;   // longest blocks first
    const int b = bh >> 4, h = bh & 15;
    const int tid = threadIdx.x;
    const int r = tid >> 2;
    const int g = tid & 3;

    const float* qbase = qkv + (size_t)b * 1024 * (3 * DMODEL) + h * DHEAD;
    const float* kbase = qbase + DMODEL;
    const float* vbase = qbase + 2 * DMODEL;

    for (int t = tid; t < 64 * 16; t += 256) {
        int row = t >> 4;
        int d4  = (t & 15) << 2;
        float4 v = *(const float4*)(qbase + (size_t)(qb * 64 + row) * (3 * DMODEL) + d4);
        *(float4*)(&Qs[row * 68 + d4]) = v;
    }

    float lsum_t = 0.f;
    float acc[16];
#pragma unroll
    for (int i = 0; i < 16; i++) acc[i] = 0.f;

    const int iglob = qb * 64 + r;
    const int nkb = 2 * (qb + 1);
    const int c0 = g * 8;
    const int dd0 = g * 16;

    const int krow = tid & 31;
    const int kd4a = (tid >> 5) << 2;
    const int kd4b = kd4a + 32;
    const int vrowa = tid >> 4;
    const int vrowb = vrowa + 16;
    const int vd4  = (tid & 15) << 2;

    float4 kreg0 = *(const float4*)(kbase + (size_t)krow * 3072 + kd4a);
    float4 kreg1 = *(const float4*)(kbase + (size_t)krow * 3072 + kd4b);
    float4 vreg0 = *(const float4*)(vbase + (size_t)vrowa * 3072 + vd4);
    float4 vreg1 = *(const float4*)(vbase + (size_t)vrowb * 3072 + vd4);

    for (int kb = 0; kb < nkb; kb++) {
        float* KT = Kt[kb & 1];
        float* VS = Vs[kb & 1];
        KT[(kd4a + 0) * 32 + krow] = kreg0.x;
        KT[(kd4a + 1) * 32 + krow] = kreg0.y;
        KT[(kd4a + 2) * 32 + krow] = kreg0.z;
        KT[(kd4a + 3) * 32 + krow] = kreg0.w;
        KT[(kd4b + 0) * 32 + krow] = kreg1.x;
        KT[(kd4b + 1) * 32 + krow] = kreg1.y;
        KT[(kd4b + 2) * 32 + krow] = kreg1.z;
        KT[(kd4b + 3) * 32 + krow] = kreg1.w;
        *(float4*)(&VS[vrowa * 64 + vd4]) = vreg0;
        *(float4*)(&VS[vrowb * 64 + vd4]) = vreg1;
        __syncthreads();

        if (kb + 1 < nkb) {
            size_t ko = (size_t)((kb + 1) * 32);
            kreg0 = *(const float4*)(kbase + (ko + krow) * 3072 + kd4a);
            kreg1 = *(const float4*)(kbase + (ko + krow) * 3072 + kd4b);
            vreg0 = *(const float4*)(vbase + (ko + vrowa) * 3072 + vd4);
            vreg1 = *(const float4*)(vbase + (ko + vrowb) * 3072 + vd4);
        }

        float s[8];
#pragma unroll
        for (int j = 0; j < 8; j++) s[j] = 0.f;
#pragma unroll 4
        for (int d = 0; d < 64; d++) {
            float qd = Qs[r * 68 + d];
            float4 k0 = *(const float4*)(&KT[d * 32 + c0]);
            float4 k1 = *(const float4*)(&KT[d * 32 + c0 + 4]);
            s[0] = fmaf(qd, k0.x, s[0]); s[1] = fmaf(qd, k0.y, s[1]);
            s[2] = fmaf(qd, k0.z, s[2]); s[3] = fmaf(qd, k0.w, s[3]);
            s[4] = fmaf(qd, k1.x, s[4]); s[5] = fmaf(qd, k1.y, s[5]);
            s[6] = fmaf(qd, k1.z, s[6]); s[7] = fmaf(qd, k1.w, s[7]);
        }
        float ls = 0.f;
#pragma unroll
        for (int j = 0; j < 8; j++) {
            int jg = kb * 32 + c0 + j;
            float p = (jg <= iglob) ? __expf(fmaf(s[j], 8.0f, -8.0f)) : 0.f;
            s[j] = p;
            ls += p;
        }
        lsum_t += ls;
        *(float4*)(&Ps[r * 36 + c0])     = make_float4(s[0], s[1], s[2], s[3]);
        *(float4*)(&Ps[r * 36 + c0 + 4]) = make_float4(s[4], s[5], s[6], s[7]);
        __syncwarp();

        for (int j = 0; j < 32; j++) {
            float p = Ps[r * 36 + j];
            const float4* v4 = (const float4*)(&VS[j * 64 + dd0]);
            float4 v0 = v4[0], v1 = v4[1], v2 = v4[2], v3 = v4[3];
            acc[0]  = fmaf(p, v0.x, acc[0]);  acc[1]  = fmaf(p, v0.y, acc[1]);
            acc[2]  = fmaf(p, v0.z, acc[2]);  acc[3]  = fmaf(p, v0.w, acc[3]);
            acc[4]  = fmaf(p, v1.x, acc[4]);  acc[5]  = fmaf(p, v1.y, acc[5]);
            acc[6]  = fmaf(p, v1.z, acc[6]);  acc[7]  = fmaf(p, v1.w, acc[7]);
            acc[8]  = fmaf(p, v2.x, acc[8]);  acc[9]  = fmaf(p, v2.y, acc[9]);
            acc[10] = fmaf(p, v2.z, acc[10]); acc[11] = fmaf(p, v2.w, acc[11]);
            acc[12] = fmaf(p, v3.x, acc[12]); acc[13] = fmaf(p, v3.y, acc[13]);
            acc[14] = fmaf(p, v3.z, acc[14]); acc[15] = fmaf(p, v3.w, acc[15]);
        }
    }

    lsum_t += __shfl_xor_sync(0xffffffffu, lsum_t, 1, 32);
    lsum_t += __shfl_xor_sync(0xffffffffu, lsum_t, 2, 32);
    float inv = 1.f / lsum_t;

    size_t obase = (size_t)(b * 1024 + iglob) * DMODEL + h * DHEAD + dd0;
#pragma unroll
    for (int q = 0; q < 4; q++) {
        float v0 = acc[q * 4]     * inv;
        float v1 = acc[q * 4 + 1] * inv;
        float v2 = acc[q * 4 + 2] * inv;
        float v3 = acc[q * 4 + 3] * inv;
        float h0 = bfr(v0), h1 = bfr(v1), h2 = bfr(v2), h3 = bfr(v3);
        *(uint2*)(oh + obase + q * 4) = make_uint2(packbf(v0, v1), packbf(v2, v3));
        *(uint2*)(ol + obase + q * 4) = make_uint2(packbf(v0 - h0, v1 - h1),
                                                   packbf(v2 - h2, v3 - h3));
    }
}

// ---------------- 3xBF16 mma.sync GEMM (2-stage, R11/R13 structure) ---------
// EPI: 1=+bias, 2=+bias+gelu->bf16 hi/lo, 3=+residual, 4=+bias+residual,
//      5=QKV: l2-normalize rows of q/k head tiles (bn<32), plain store for v.
template<int EPI, int BN>
__global__ __launch_bounds__(256, 2) void hgemm2_kernel(
    const __nv_bfloat16* __restrict__ Ah_g, const __nv_bfloat16* __restrict__ Al_g,
    const __nv_bfloat16* __restrict__ Bh_g, const __nv_bfloat16* __restrict__ Bl_g,
    float* __restrict__ C,
    __nv_bfloat16* __restrict__ Ch, __nv_bfloat16* __restrict__ Cl,
    int K, int N, const float* __restrict__ bias, const float* __restrict__ res)
{
    constexpr int      BP     = (BN == 128) ? 136 : 72;
    constexpr int      NT     = BN / 16;
    constexpr uint32_t AL_OFF = 10240;
    constexpr uint32_t BH_OFF = 20480;
    constexpr uint32_t BBYT   = 32u * BP * 2u;
    constexpr uint32_t STG    = BH_OFF + 2u * BBYT;

    extern __shared__ char smem[];
    __shared__ float rnorm[128];
    const uint32_t sbase = s2u(smem);
    const int tid  = threadIdx.x;
    const int bn   = blockIdx.x, bm = blockIdx.y;
    const int lane = tid & 31, warp = tid >> 5;
    const int wm   = warp & 3;
    const int wn   = warp >> 2;

    float acc[2][NT][4] = {};

    const int ar0 = tid >> 2;
    const int as0 = (tid & 3) * 8;
    const __nv_bfloat16* gAh0 = Ah_g + (size_t)(bm * 128 + ar0) * K + as0;
    const __nv_bfloat16* gAh1 = gAh0 + (size_t)64 * K;
    const __nv_bfloat16* gAl0 = Al_g + (size_t)(bm * 128 + ar0) * K + as0;
    const __nv_bfloat16* gAl1 = gAl0 + (size_t)64 * K;
    const uint32_t dA0 = sbase + (uint32_t)(ar0 * 40 + as0) * 2;
    const uint32_t dA1 = sbase + (uint32_t)((ar0 + 64) * 40 + as0) * 2;

    const int bk0 = (BN == 128) ? (tid >> 4) : (tid >> 3);
    const int bs0 = (BN == 128) ? (tid & 15) * 8 : (tid & 7) * 8;
    const __nv_bfloat16* gBh0 = Bh_g + (size_t)bk0 * N + (size_t)bn * BN + bs0;
    const __nv_bfloat16* gBh1 = gBh0 + (size_t)16 * N;
    const __nv_bfloat16* gBl0 = Bl_g + (size_t)bk0 * N + (size_t)bn * BN + bs0;
    const __nv_bfloat16* gBl1 = gBl0 + (size_t)16 * N;
    const uint32_t dB0 = sbase + BH_OFF + (uint32_t)(bk0 * BP + bs0) * 2;
    const uint32_t dB1 = sbase + BH_OFF + (uint32_t)((bk0 + 16) * BP + bs0) * 2;

#define ISSUE_STAGE(stage, kt) do {                                            \
        uint32_t sb_ = (uint32_t)(stage) * STG;                                \
        size_t ko_ = (size_t)(kt);                                             \
        size_t kb_ = (size_t)(kt) * (size_t)N;                                 \
        CP16(dA0 + sb_,           gAh0 + ko_);                                 \
        CP16(dA1 + sb_,           gAh1 + ko_);                                 \
        CP16(dA0 + sb_ + AL_OFF,  gAl0 + ko_);                                 \
        CP16(dA1 + sb_ + AL_OFF,  gAl1 + ko_);                                 \
        CP16(dB0 + sb_,           gBh0 + kb_);                                 \
        CP16(dB0 + sb_ + BBYT,    gBl0 + kb_);                                 \
        if (BN == 128) {                                                       \
            CP16(dB1 + sb_,        gBh1 + kb_);                                \
            CP16(dB1 + sb_ + BBYT, gBl1 + kb_);                                \
        }                                                                      \
        CPCOMMIT();                                                            \
    } while (0)

    uint32_t aH[2], aL[2], bHa[NT / 2], bLa[NT / 2];
    {
        int r = wm * 32 + (lane & 7) + ((lane >> 3) & 1) * 8;
        int c = (lane >> 4) * 8;
        aH[0] = sbase + (uint32_t)(r * 40 + c) * 2;
        aH[1] = sbase + (uint32_t)((r + 16) * 40 + c) * 2;
        aL[0] = aH[0] + AL_OFF;
        aL[1] = aH[1] + AL_OFF;
        int br = (lane & 7) + ((lane >> 3) & 1) * 8;
        int bc = wn * (BN / 2) + (lane >> 4) * 8;
#pragma unroll
        for (int p = 0; p < NT / 2; p++) {
            bHa[p] = sbase + BH_OFF + (uint32_t)(br * BP + bc + p * 16) * 2;
            bLa[p] = bHa[p] + BBYT;
        }
    }

    const int nc = K >> 5;
    ISSUE_STAGE(0, 0);

    for (int cchunk = 0; cchunk < nc; cchunk++) {
        const uint32_t sb = (uint32_t)(cchunk & 1) * STG;
        CPWAIT(0);
        __syncthreads();
        if (cchunk + 1 < nc) ISSUE_STAGE((cchunk + 1) & 1, (cchunk + 1) * 32);

#pragma unroll
        for (int ks = 0; ks < 2; ks++) {
            const uint32_t ao = sb + ks * 32;
            const uint32_t bo = sb + ks * (16u * BP * 2u);
            uint32_t a_h[2][4], a_l[2][4], bfrg[NT / 2][4];
            LDMX4(a_h[0], aH[0] + ao);
            LDMX4(a_h[1], aH[1] + ao);
            LDMX4(a_l[0], aL[0] + ao);
            LDMX4(a_l[1], aL[1] + ao);
#pragma unroll
            for (int p = 0; p < NT / 2; p++) LDMX4T(bfrg[p], bHa[p] + bo);
#pragma unroll
            for (int mt = 0; mt < 2; mt++)
#pragma unroll
                for (int nt = 0; nt < NT; nt++) {
                    uint32_t b0 = bfrg[nt >> 1][(nt & 1) * 2];
                    uint32_t b1 = bfrg[nt >> 1][(nt & 1) * 2 + 1];
                    MMA16816(acc[mt][nt], a_h[mt], b0, b1);
                    MMA16816(acc[mt][nt], a_l[mt], b0, b1);
                }
#pragma unroll
            for (int p = 0; p < NT / 2; p++) LDMX4T(bfrg[p], bLa[p] + bo);
#pragma unroll
            for (int mt = 0; mt < 2; mt++)
#pragma unroll
                for (int nt = 0; nt < NT; nt++) {
                    uint32_t b0 = bfrg[nt >> 1][(nt & 1) * 2];
                    uint32_t b1 = bfrg[nt >> 1][(nt & 1) * 2 + 1];
                    MMA16816(acc[mt][nt], a_h[mt], b0, b1);
                }
        }
    }
#undef ISSUE_STAGE

    const int g  = lane >> 2;
    const int tg = lane & 3;

    if (EPI == 5) {
        // QKV epilogue: l2-normalize q/k head rows (one head per BN=64 tile).
        const bool dn = (bn < 32);
        if (dn) {
            if (tid < 128) rnorm[tid] = 0.f;
            __syncthreads();
#pragma unroll
            for (int mt = 0; mt < 2; mt++) {
                float s0 = 0.f, s1 = 0.f;
#pragma unroll
                for (int nt = 0; nt < NT; nt++) {
                    s0 += acc[mt][nt][0] * acc[mt][nt][0]
                        + acc[mt][nt][1] * acc[mt][nt][1];
                    s1 += acc[mt][nt][2] * acc[mt][nt][2]
                        + acc[mt][nt][3] * acc[mt][nt][3];
                }
                int rl = wm * 32 + mt * 16 + g;
                atomicAdd(&rnorm[rl], s0);
                atomicAdd(&rnorm[rl + 8], s1);
            }
            __syncthreads();
        }
#pragma unroll
        for (int mt = 0; mt < 2; mt++) {
            int rl = wm * 32 + mt * 16 + g;
            int row = bm * 128 + rl;
            float i0 = dn ? rsqrtf(rnorm[rl])     : 1.f;
            float i1 = dn ? rsqrtf(rnorm[rl + 8]) : 1.f;
#pragma unroll
            for (int nt = 0; nt < NT; nt++) {
                int col = bn * BN + wn * (BN / 2) + nt * 8 + tg * 2;
                size_t off0 = (size_t)row * N + col;
                size_t off1 = (size_t)(row + 8) * N + col;
                *(float2*)(C + off0) = make_float2(acc[mt][nt][0] * i0,
                                                   acc[mt][nt][1] * i0);
                *(float2*)(C + off1) = make_float2(acc[mt][nt][2] * i1,
                                                   acc[mt][nt][3] * i1);
            }
        }
    } else {
#pragma unroll
        for (int mt = 0; mt < 2; mt++) {
            int row = bm * 128 + wm * 32 + mt * 16 + g;
#pragma unroll
            for (int nt = 0; nt < NT; nt++) {
                int col = bn * BN + wn * (BN / 2) + nt * 8 + tg * 2;
                float d0 = acc[mt][nt][0], d1 = acc[mt][nt][1];
                float d2 = acc[mt][nt][2], d3 = acc[mt][nt][3];
                if (EPI == 1 || EPI == 2 || EPI == 4) {
                    float2 bb = *(const float2*)(bias + col);
                    d0 += bb.x; d1 += bb.y; d2 += bb.x; d3 += bb.y;
                }
                size_t off0 = (size_t)row * N + col;
                size_t off1 = (size_t)(row + 8) * N + col;
                if (EPI == 2) {
                    d0 = geluf(d0); d1 = geluf(d1); d2 = geluf(d2); d3 = geluf(d3);
                    float h0 = bfr(d0), h1 = bfr(d1), h2 = bfr(d2), h3 = bfr(d3);
                    *(uint32_t*)(Ch + off0) = packbf(d0, d1);
                    *(uint32_t*)(Cl + off0) = packbf(d0 - h0, d1 - h1);
                    *(uint32_t*)(Ch + off1) = packbf(d2, d3);
                    *(uint32_t*)(Cl + off1) = packbf(d2 - h2, d3 - h3);
                } else {
                    if (EPI == 3 || EPI == 4) {
                        float2 r0 = *(const float2*)(res + off0);
                        float2 r1 = *(const float2*)(res + off1);
                        d0 += r0.x; d1 += r0.y; d2 += r1.x; d3 += r1.y;
                    }
                    *(float2*)(C + off0) = make_float2(d0, d1);
                    *(float2*)(C + off1) = make_float2(d2, d3);
                }
            }
        }
    }
}

// ---------------- 2xFP16 mma.sync GEMM for logits ---------------------------
// Grid: (bm, bn) with bm fastest so consecutive CTAs share the B tile in L2.
__global__ __launch_bounds__(256, 2) void hgemm_h2_kernel(
    const __half* __restrict__ Ah_g, const __half* __restrict__ Al_g,
    const __half* __restrict__ Bh_g, float* __restrict__ C,
    int K, int N, const float* __restrict__ bias)
{
    constexpr int      BP     = 136;
    constexpr uint32_t AL_OFF = 10240;
    constexpr uint32_t BH_OFF = 20480;
    constexpr uint32_t BBYT   = 32u * BP * 2u;     // 8704
    constexpr uint32_t STG    = BH_OFF + BBYT;     // 29184

    extern __shared__ char smem[];
    const uint32_t sbase = s2u(smem);
    const int tid  = threadIdx.x;
    const int bm   = blockIdx.x, bn = blockIdx.y;   // bm fastest: B-tile L2 reuse
    const int lane = tid & 31, warp = tid >> 5;
    const int wm   = warp & 3;
    const int wn   = warp >> 2;

    float acc[2][8][4] = {};

    const int ar0 = tid >> 2;
    const int as0 = (tid & 3) * 8;
    const __half* gAh0 = Ah_g + (size_t)(bm * 128 + ar0) * K + as0;
    const __half* gAh1 = gAh0 + (size_t)64 * K;
    const __half* gAl0 = Al_g + (size_t)(bm * 128 + ar0) * K + as0;
    const __half* gAl1 = gAl0 + (size_t)64 * K;
    const uint32_t dA0 = sbase + (uint32_t)(ar0 * 40 + as0) * 2;
    const uint32_t dA1 = sbase + (uint32_t)((ar0 + 64) * 40 + as0) * 2;

    const int bk0 = tid >> 4;
    const int bs0 = (tid & 15) * 8;
    const __half* gBh0 = Bh_g + (size_t)bk0 * N + (size_t)bn * 128 + bs0;
    const __half* gBh1 = gBh0 + (size_t)16 * N;
    const uint32_t dB0 = sbase + BH_OFF + (uint32_t)(bk0 * BP + bs0) * 2;
    const uint32_t dB1 = sbase + BH_OFF + (uint32_t)((bk0 + 16) * BP + bs0) * 2;

#define ISSUE_H(stage, kt) do {                                                \
        uint32_t sb_ = (uint32_t)(stage) * STG;                                \
        size_t ko_ = (size_t)(kt);                                             \
        size_t kb_ = (size_t)(kt) * (size_t)N;                                 \
        CP16(dA0 + sb_,          gAh0 + ko_);                                  \
        CP16(dA1 + sb_,          gAh1 + ko_);                                  \
        CP16(dA0 + sb_ + AL_OFF, gAl0 + ko_);                                  \
        CP16(dA1 + sb_ + AL_OFF, gAl1 + ko_);                                  \
        CP16(dB0 + sb_,          gBh0 + kb_);                                  \
        CP16(dB1 + sb_,          gBh1 + kb_);                                  \
        CPCOMMIT();                                                            \
    } while (0)

    uint32_t aH[2], aL[2], bHa[4];
    {
        int r = wm * 32 + (lane & 7) + ((lane >> 3) & 1) * 8;
        int c = (lane >> 4) * 8;
        aH[0] = sbase + (uint32_t)(r * 40 + c) * 2;
        aH[1] = sbase + (uint32_t)((r + 16) * 40 + c) * 2;
        aL[0] = aH[0] + AL_OFF;
        aL[1] = aH[1] + AL_OFF;
        int br = (lane & 7) + ((lane >> 3) & 1) * 8;
        int bc = wn * 64 + (lane >> 4) * 8;
#pragma unroll
        for (int p = 0; p < 4; p++)
            bHa[p] = sbase + BH_OFF + (uint32_t)(br * BP + bc + p * 16) * 2;
    }

    const int nc = K >> 5;
    ISSUE_H(0, 0);

    for (int cchunk = 0; cchunk < nc; cchunk++) {
        const uint32_t sb = (uint32_t)(cchunk & 1) * STG;
        CPWAIT(0);
        __syncthreads();
        if (cchunk + 1 < nc) ISSUE_H((cchunk + 1) & 1, (cchunk + 1) * 32);

#pragma unroll
        for (int ks = 0; ks < 2; ks++) {
            const uint32_t ao = sb + ks * 32;
            const uint32_t bo = sb + ks * (16u * BP * 2u);
            uint32_t a_h[2][4], a_l[2][4], bfrg[4][4];
            LDMX4(a_h[0], aH[0] + ao);
            LDMX4(a_h[1], aH[1] + ao);
            LDMX4(a_l[0], aL[0] + ao);
            LDMX4(a_l[1], aL[1] + ao);
#pragma unroll
            for (int p = 0; p < 4; p++) LDMX4T(bfrg[p], bHa[p] + bo);
#pragma unroll
            for (int mt = 0; mt < 2; mt++)
#pragma unroll
                for (int nt = 0; nt < 8; nt++) {
                    uint32_t b0 = bfrg[nt >> 1][(nt & 1) * 2];
                    uint32_t b1 = bfrg[nt >> 1][(nt & 1) * 2 + 1];
                    MMAF16(acc[mt][nt], a_h[mt], b0, b1);
                    MMAF16(acc[mt][nt], a_l[mt], b0, b1);
                }
        }
    }
#undef ISSUE_H

    const int g  = lane >> 2;
    const int tg = lane & 3;
#pragma unroll
    for (int mt = 0; mt < 2; mt++) {
        int row = bm * 128 + wm * 32 + mt * 16 + g;
#pragma unroll
        for (int nt = 0; nt < 8; nt++) {
            int col = bn * 128 + wn * 64 + nt * 8 + tg * 2;
            float2 bb = *(const float2*)(bias + col);
            float d0 = acc[mt][nt][0] + bb.x, d1 = acc[mt][nt][1] + bb.y;
            float d2 = acc[mt][nt][2] + bb.x, d3 = acc[mt][nt][3] + bb.y;
            size_t off0 = (size_t)row * N + col;
            size_t off1 = (size_t)(row + 8) * N + col;
            *(float2*)(C + off0) = make_float2(d0, d1);
            *(float2*)(C + off1) = make_float2(d2, d3);
        }
    }
}

#define STG128 (20480u + 2u * (32u * 136u * 2u))   // 37888
#define STG64  (20480u + 2u * (32u * 72u  * 2u))   // 29696
#define GSMEM128 (2 * STG128)                      // 75776
#define GSMEM64  (2 * STG64)                       // 59392 (2-stage, 2 CTAs/SM safe)
#define GSMEMH   (2 * 29184u)                      // 58368

// ---------------- launch ----------------
extern "C" void kernel_launch(void* const* d_in, const int* in_sizes, int n_in,
                              void* d_out, int out_size)
{
    const int*   x       = (const int*)  d_in[0];
    const float* tok     = (const float*)d_in[1];
    const float* pos     = (const float*)d_in[2];
    const float* ln1_g   = (const float*)d_in[3];
    const float* ln1_b   = (const float*)d_in[4];
    const float* w_qkv   = (const float*)d_in[5];
    const float* w_out   = (const float*)d_in[6];
    const float* ln2_g   = (const float*)d_in[7];
    const float* ln2_b   = (const float*)d_in[8];
    const float* w1      = (const float*)d_in[9];
    const float* b1      = (const float*)d_in[10];
    const float* w2      = (const float*)d_in[11];
    const float* b2      = (const float*)d_in[12];
    const float* lnf_g   = (const float*)d_in[13];
    const float* lnf_b   = (const float*)d_in[14];
    const float* w_logit = (const float*)d_in[15];
    const float* b_logit = (const float*)d_in[16];
    float* out = (float*)d_out;

    void *ph, *pqkv, *pxnh, *pxnl, *poh, *pol, *pffh, *pffl, *pwh, *pwl;
    cudaGetSymbolAddress(&ph,   g_h);
    cudaGetSymbolAddress(&pqkv, g_qkv);
    cudaGetSymbolAddress(&pxnh, g_xnh);
    cudaGetSymbolAddress(&pxnl, g_xnl);
    cudaGetSymbolAddress(&poh,  g_oh);
    cudaGetSymbolAddress(&pol,  g_ol);
    cudaGetSymbolAddress(&pffh, g_ffh);
    cudaGetSymbolAddress(&pffl, g_ffl);
    cudaGetSymbolAddress(&pwh,  g_wh);
    cudaGetSymbolAddress(&pwl,  g_wl);
    float* h   = (float*)ph;
    float* qkv = (float*)pqkv;
    __nv_bfloat16* xnh = (__nv_bfloat16*)pxnh;
    __nv_bfloat16* xnl = (__nv_bfloat16*)pxnl;
    __nv_bfloat16* oh  = (__nv_bfloat16*)poh;
    __nv_bfloat16* ol  = (__nv_bfloat16*)pol;
    __nv_bfloat16* ffh = (__nv_bfloat16*)pffh;
    __nv_bfloat16* ffl = (__nv_bfloat16*)pffl;
    __nv_bfloat16* wh  = (__nv_bfloat16*)pwh;
    __nv_bfloat16* wl  = (__nv_bfloat16*)pwl;
    __half* xh2 = (__half*)pffh;
    __half* xl2 = (__half*)pffl;
    __half* wlh = (__half*)(wh + OFF_WLOG);

    cudaFuncSetAttribute(hgemm2_kernel<5,64>,  cudaFuncAttributeMaxDynamicSharedMemorySize, GSMEM64);
    cudaFuncSetAttribute(hgemm2_kernel<3,64>,  cudaFuncAttributeMaxDynamicSharedMemorySize, GSMEM64);
    cudaFuncSetAttribute(hgemm2_kernel<4,64>,  cudaFuncAttributeMaxDynamicSharedMemorySize, GSMEM64);
    cudaFuncSetAttribute(hgemm2_kernel<2,128>, cudaFuncAttributeMaxDynamicSharedMemorySize, GSMEM128);
    cudaFuncSetAttribute(hgemm_h2_kernel,      cudaFuncAttributeMaxDynamicSharedMemorySize, GSMEMH);

    // ---- weight splitting (once per launch) ----
    wcvt_kernel<<<(CNT_QKV  / 4 + 255) / 256, 256>>>(w_qkv,   wh + OFF_QKV,  wl + OFF_QKV,  CNT_QKV  / 4);
    wcvt_kernel<<<(CNT_WOUT / 4 + 255) / 256, 256>>>(w_out,   wh + OFF_WOUT, wl + OFF_WOUT, CNT_WOUT / 4);
    wcvt_kernel<<<(CNT_W1   / 4 + 255) / 256, 256>>>(w1,      wh + OFF_W1,   wl + OFF_W1,   CNT_W1   / 4);
    wcvt_kernel<<<(CNT_W2   / 4 + 255) / 256, 256>>>(w2,      wh + OFF_W2,   wl + OFF_W2,   CNT_W2   / 4);
    wcvt_h_kernel<<<(CNT_WLOG / 4 + 255) / 256, 256>>>(w_logit, wlh, CNT_WLOG / 4);

    embed_kernel<<<2048, 256>>>(x, tok, pos, h);

    for (int l = 0; l < NLAYER; l++) {
        ln_kernel<<<NROWS, 256>>>(h, xnh, xnl, ln1_g + l * DMODEL, ln1_b + l * DMODEL);
        // QKV with fused q/k l2norm in epilogue (EPI=5)
        hgemm2_kernel<5,64><<<dim3(3072 / 64, NROWS / 128), 256, GSMEM64>>>(
            xnh, xnl, wh + OFF_QKV + (size_t)l * 1024 * 3072, wl + OFF_QKV + (size_t)l * 1024 * 3072,
            qkv, nullptr, nullptr, DMODEL, 3072, nullptr, nullptr);
        flash_kernel<<<dim3(32, 16), 256>>>(qkv, oh, ol);
        hgemm2_kernel<3,64><<<dim3(DMODEL / 64, NROWS / 128), 256, GSMEM64>>>(
            oh, ol, wh + OFF_WOUT + (size_t)l * 1024 * 1024, wl + OFF_WOUT + (size_t)l * 1024 * 1024,
            h, nullptr, nullptr, DMODEL, DMODEL, nullptr, h);
        ln_kernel<<<NROWS, 256>>>(h, xnh, xnl, ln2_g + l * DMODEL, ln2_b + l * DMODEL);
        hgemm2_kernel<2,128><<<dim3(DFF / 128, NROWS / 128), 256, GSMEM128>>>(
            xnh, xnl, wh + OFF_W1 + (size_t)l * 1024 * 4096, wl + OFF_W1 + (size_t)l * 1024 * 4096,
            nullptr, ffh, ffl, DMODEL, DFF, b1 + l * DFF, nullptr);
        hgemm2_kernel<4,64><<<dim3(DMODEL / 64, NROWS / 128), 256, GSMEM64>>>(
            ffh, ffl, wh + OFF_W2 + (size_t)l * 1024 * 4096, wl + OFF_W2 + (size_t)l * 1024 * 4096,
            h, nullptr, nullptr, DFF, DMODEL, b2 + l * DMODEL, h);
    }

    // final LN -> fp16 hi/lo (ff buffers are dead after the last layer)
    ln_h_kernel<<<NROWS, 256>>>(h, xh2, xl2, lnf_g, lnf_b);
    // logits: bm fastest for B-tile L2 reuse
    hgemm_h2_kernel<<<dim3(NROWS / 128, NVOCAB / 128), 256, GSMEMH>>>(
        xh2, xl2, wlh, out, DMODEL, NVOCAB, b_logit);
}